// round 10
// baseline (speedup 1.0000x reference)
#include <cuda_runtime.h>
#include <cuda_fp16.h>
#include <math.h>
#include <stdint.h>

// Problem dims
#define T_DIM 512
#define B_DIM 32
#define E_DIM 512
#define H_DIM 2048

// GEMM tiling: CTA = 128 threads (4 warps, 2M x 2N), warp tile 32x48, CTA tile 64x96
#define HC  32          // h channels per CTA
#define NT  96          // GEMM N = 3*HC (z|f|o)
#define MT  64          // t-chunk (GEMM M)
#define KC  64          // K elems per smem chunk (fp16 -> 128B rows)
#define NKC 8           // K chunks per t-chunk (512/64)
#define NTC 8           // t-chunks (512/64)
#define NCH (NTC * NKC) // 64 chunks total

// ---- GEMM kernel smem layout (bytes) ----
#define SM_A    0                    // 2 x 8192   (A stages, fp16 SW128)
#define SM_B    16384                // 2 x 12288  (W stages, fp16 SW128)
#define SM_BIAS 40960                // 96 floats = 384
#define SMEM_GEMM 41344              // x4 CTAs = 165KB

// ---- scan kernel smem layout ----
#define S_T      128                 // t per scan chunk
#define S_STRIDE 104                 // halves per t row (96 + 8 pad)
#define S_BUF    26624               // 128 x 104 x 2 bytes
#define SM2_SEGA 53248               // 4 x 32 floats
#define SM2_SEGB 53760               // 4 x 32 floats
#define SMEM_SCAN 54272              // x4 CTAs = 212KB

#define SWZ128(x) ((x) ^ (((x) >> 3) & 0x70))

// static device scratch (allowed)
__device__ __half g_sentH[B_DIM * T_DIM * E_DIM];          // (B,T,E) fp16
__device__ __half g_wH[3 * H_DIM * E_DIM];                 // (3H,E)  fp16
__device__ __half g_act[(size_t)B_DIM * 3 * T_DIM * H_DIM];// (B,3,T,H) fp16 activations

// ---------------- helpers ----------------
__device__ __forceinline__ uint32_t smem_u32(const void* p) {
    uint32_t a;
    asm("{ .reg .u64 t; cvta.to.shared.u64 t, %1; cvt.u32.u64 %0, t; }" : "=r"(a) : "l"(p));
    return a;
}
__device__ __forceinline__ float tanh_hw(float x) {
    float y; asm("tanh.approx.f32 %0, %1;" : "=f"(y) : "f"(x)); return y;
}
__device__ __forceinline__ float sigmoid_hw(float x) {
    return fmaf(0.5f, tanh_hw(0.5f * x), 0.5f);
}
__device__ __forceinline__ void cp_async16(uint32_t dst, const void* src) {
    uint64_t g; asm("cvta.to.global.u64 %0, %1;" : "=l"(g) : "l"(src));
    asm volatile("cp.async.cg.shared.global [%0], [%1], 16;" :: "r"(dst), "l"(g) : "memory");
}
__device__ __forceinline__ void ldsm4(uint32_t* r, uint32_t addr) {
    asm volatile("ldmatrix.sync.aligned.m8n8.x4.shared.b16 {%0,%1,%2,%3}, [%4];"
                 : "=r"(r[0]), "=r"(r[1]), "=r"(r[2]), "=r"(r[3]) : "r"(addr));
}
__device__ __forceinline__ void mma_f16(float* c, const uint32_t* a, const uint32_t* b) {
    asm volatile(
        "mma.sync.aligned.m16n8k16.row.col.f32.f16.f16.f32 "
        "{%0,%1,%2,%3}, {%4,%5,%6,%7}, {%8,%9}, {%0,%1,%2,%3};"
        : "+f"(c[0]), "+f"(c[1]), "+f"(c[2]), "+f"(c[3])
        : "r"(a[0]), "r"(a[1]), "r"(a[2]), "r"(a[3]), "r"(b[0]), "r"(b[1]));
}

// ---------- merged prepass: fp32 -> fp16; sent also transposed (T,B,E)->(B,T,E) ----------
#define SENT_F4 (T_DIM * B_DIM * E_DIM / 4)   // 2,097,152
#define W_F4    (3 * H_DIM * E_DIM / 4)       //   786,432
__global__ void __launch_bounds__(256) prep_all(const float* __restrict__ sent,
                                                const float* __restrict__ W) {
    int li = blockIdx.x * 256 + threadIdx.x;
    if (li < SENT_F4) {
        const float4 v = ((const float4*)sent)[li];
        int e4 = li & 127;
        int b  = (li >> 7) & 31;
        int t  = li >> 12;
        __half2* dst = (__half2*)(g_sentH + ((size_t)(b * T_DIM + t) * E_DIM + e4 * 4));
        dst[0] = __floats2half2_rn(v.x, v.y);
        dst[1] = __floats2half2_rn(v.z, v.w);
    } else if (li < SENT_F4 + W_F4) {
        int wi = li - SENT_F4;
        const float4 v = ((const float4*)W)[wi];
        __half2* dst = (__half2*)g_wH + (size_t)wi * 2;
        dst[0] = __floats2half2_rn(v.x, v.y);
        dst[1] = __floats2half2_rn(v.z, v.w);
    }
}

// ============ GEMM kernel: pure GEMM + activation + STG; 1 sync per chunk ============
__global__ void __launch_bounds__(128, 4)
qrnn_gemm_kernel(const float* __restrict__ bias)
{
    extern __shared__ char smem[];
    const uint32_t sb = smem_u32(smem);
    const int tid = threadIdx.x;
    const int bb  = blockIdx.y;
    const int h0  = blockIdx.x * HC;
    const int lane = tid & 31;
    const int wid  = tid >> 5;
    const int g  = lane >> 2;
    const int tg = lane & 3;
    const int wm = wid & 1;          // 2 warps in M
    const int wn = wid >> 1;         // 2 warps in N
    const int m_base = wm * 32;
    const int n_base = wn * 48;

    float* sbias = (float*)(smem + SM_BIAS);
    if (tid < 96) sbias[tid] = bias[(tid >> 5) * H_DIM + h0 + (tid & 31)];

    const __half* Asrc = g_sentH + (size_t)bb * (T_DIM * E_DIM);

    const int am = lane >> 3;
    const int a_row_in = (am & 1) * 8 + (lane & 7);
    const int a_colb16 = (am >> 1) * 16;
    const int b_row_in = (am >> 1) * 8 + (lane & 7);
    const int b_colb16 = (am & 1) * 16;

    auto stage = [&](int ch) {
        const int tc = ch >> 3, kc = ch & 7, buf = ch & 1;
        const __half* ab = Asrc + (size_t)(tc * MT) * E_DIM + kc * KC;
        const uint32_t aB = sb + SM_A + buf * 8192;
#pragma unroll
        for (int i = 0; i < 4; i++) {
            int l = i * 128 + tid;
            int row = l >> 3, c = l & 7;
            cp_async16(aB + (uint32_t)SWZ128(row * 128 + c * 16), ab + (size_t)row * E_DIM + c * 8);
        }
        const uint32_t bB = sb + SM_B + buf * 12288;
#pragma unroll
        for (int i = 0; i < 6; i++) {
            int l = i * 128 + tid;
            int n = l >> 3, c = l & 7;
            int wrow = (n >> 5) * H_DIM + h0 + (n & 31);
            cp_async16(bB + (uint32_t)SWZ128(n * 128 + c * 16),
                       g_wH + (size_t)wrow * E_DIM + kc * KC + c * 8);
        }
        asm volatile("cp.async.commit_group;" ::: "memory");
    };

    stage(0);

    for (int tc = 0; tc < NTC; tc++) {
        float acc[2][6][4];
#pragma unroll
        for (int mf = 0; mf < 2; mf++)
#pragma unroll
            for (int nf = 0; nf < 6; nf++)
#pragma unroll
                for (int q = 0; q < 4; q++) acc[mf][nf][q] = 0.0f;

        for (int kc = 0; kc < NKC; kc++) {
            const int ch  = tc * NKC + kc;
            const int buf = ch & 1;

            asm volatile("cp.async.wait_group 0;" ::: "memory");
            __syncthreads();   // chunk ch visible to all; chunk ch-1's readers done
            if (ch + 1 < NCH) stage(ch + 1);   // fills other buffer, overlaps MMAs

            const uint32_t aB = sb + SM_A + buf * 8192;
            const uint32_t bB = sb + SM_B + buf * 12288;
#pragma unroll
            for (int ks = 0; ks < 4; ks++) {     // 4 k16-steps over KC=64
                uint32_t a[2][4];
#pragma unroll
                for (int mf = 0; mf < 2; mf++) {
                    int row  = m_base + mf * 16 + a_row_in;
                    int colb = ks * 32 + a_colb16;
                    ldsm4(a[mf], aB + (uint32_t)SWZ128(row * 128 + colb));
                }
                uint32_t b[6][2];
#pragma unroll
                for (int p = 0; p < 3; p++) {
                    int nrow = n_base + p * 16 + b_row_in;
                    int colb = ks * 32 + b_colb16;
                    uint32_t r[4];
                    ldsm4(r, bB + (uint32_t)SWZ128(nrow * 128 + colb));
                    b[2 * p][0] = r[0];     b[2 * p][1] = r[1];
                    b[2 * p + 1][0] = r[2]; b[2 * p + 1][1] = r[3];
                }
#pragma unroll
                for (int mf = 0; mf < 2; mf++)
#pragma unroll
                    for (int nf = 0; nf < 6; nf++)
                        mma_f16(acc[mf][nf], a[mf], b[nf]);
            }
        }

        // ---- epilogue: bias + activation -> STG fp16 to g_act[b][grp][t][h]; no syncs ----
#pragma unroll
        for (int mf = 0; mf < 2; mf++) {
            int r0 = m_base + mf * 16 + g;
#pragma unroll
            for (int nf = 0; nf < 6; nf++) {
                int j    = n_base + nf * 8 + tg * 2;
                int grp  = j >> 5;
                int hcol = j & 31;
                __half* outp = g_act + (((size_t)(bb * 3 + grp) * T_DIM) * H_DIM) + h0 + hcol;
#pragma unroll
                for (int rr = 0; rr < 2; rr++) {
                    int t    = tc * MT + r0 + rr * 8;
                    float v0 = acc[mf][nf][rr * 2 + 0] + sbias[j];
                    float v1 = acc[mf][nf][rr * 2 + 1] + sbias[j + 1];
                    if (grp == 0) { v0 = tanh_hw(v0);    v1 = tanh_hw(v1); }
                    else          { v0 = sigmoid_hw(v0); v1 = sigmoid_hw(v1); }
                    *(__half2*)(outp + (size_t)t * H_DIM) = __floats2half2_rn(v0, v1);
                }
            }
        }
    }
}

// ============ scan kernel: CTA = (b, 32h); streaming chunks of 128 t ============
__global__ void __launch_bounds__(128, 4)
qrnn_scan_kernel(float* __restrict__ out)
{
    extern __shared__ char smem[];
    const uint32_t sb = smem_u32(smem);
    const int tid = threadIdx.x;
    const int bb  = blockIdx.y;
    const int h0  = blockIdx.x * HC;
    const int lane = tid & 31;
    const int wid  = tid >> 5;       // 0..3, owns t-segment [32*wid, 32*wid+32)

    float* segA = (float*)(smem + SM2_SEGA);   // [4][32]
    float* segB = (float*)(smem + SM2_SEGB);   // [4][32]

    // stage scan chunk ck (128 t x 96 ch fp16) into buffer buf
    auto sstage = [&](int ck, int buf) {
        const uint32_t dB = sb + buf * S_BUF;
#pragma unroll
        for (int i = 0; i < 12; i++) {        // 1536 x 16B ops
            int l   = i * 128 + tid;
            int c   = l & 3;                  // 16B sub-chunk within 64B row-part
            int row = l >> 2;                 // 0..383: grp*128 + t
            int grp = row >> 7;
            int t   = row & 127;
            const __half* src = g_act + ((size_t)(bb * 3 + grp) * T_DIM + ck * S_T + t) * H_DIM
                              + h0 + c * 8;
            cp_async16(dB + t * (S_STRIDE * 2) + grp * 64 + c * 16, src);
        }
        asm volatile("cp.async.commit_group;" ::: "memory");
    };

    float c_carry = 0.0f;
    float m_state = -INFINITY;

    sstage(0, 0);

    for (int ck = 0; ck < T_DIM / S_T; ck++) {
        asm volatile("cp.async.wait_group 0;" ::: "memory");
        __syncthreads();                  // chunk ck visible; previous chunk's readers done
        if (ck + 1 < T_DIM / S_T) sstage(ck + 1, (ck + 1) & 1);

        const __half* act = (const __half*)(smem + (ck & 1) * S_BUF);
        const int t0s = wid * 32;

        // pass 1: per-segment affine composition
        float Aseg = 1.0f, Bseg = 0.0f;
#pragma unroll 8
        for (int i = 0; i < 32; i++) {
            const __half* rowp = act + (t0s + i) * S_STRIDE;
            float z = __half2float(rowp[lane]);
            float f = __half2float(rowp[32 + lane]);
            float a = 1.0f - f;
            Aseg *= a;
            Bseg = fmaf(a, Bseg, f * z);
        }
        segA[wid * 32 + lane] = Aseg;
        segB[wid * 32 + lane] = Bseg;
        __syncthreads();

        // entry state for my segment
        float c = c_carry;
        for (int s = 0; s < wid; s++)
            c = fmaf(segA[s * 32 + lane], c, segB[s * 32 + lane]);
        // pass 2: walk my 32 t's
#pragma unroll 8
        for (int i = 0; i < 32; i++) {
            const __half* rowp = act + (t0s + i) * S_STRIDE;
            float z = __half2float(rowp[lane]);
            float f = __half2float(rowp[32 + lane]);
            float o = __half2float(rowp[64 + lane]);
            c = fmaf(f, z - c, c);
            m_state = fmaxf(m_state, o * c);
        }
        // advance carry (replicated across warps)
#pragma unroll
        for (int s = 0; s < 4; s++)
            c_carry = fmaf(segA[s * 32 + lane], c_carry, segB[s * 32 + lane]);
        // next iteration's top barrier orders these reads before seg overwrite
    }

    __syncthreads();
    segA[wid * 32 + lane] = m_state;
    __syncthreads();
    if (wid == 0) {
        float r = m_state;
#pragma unroll
        for (int s = 1; s < 4; s++) r = fmaxf(r, segA[s * 32 + lane]);
        out[bb * H_DIM + h0 + lane] = r;
    }
}

extern "C" void kernel_launch(void* const* d_in, const int* in_sizes, int n_in,
                              void* d_out, int out_size)
{
    (void)in_sizes; (void)n_in; (void)out_size;
    const float* sent = (const float*)d_in[0];   // (T,B,E) fp32
    const float* W    = (const float*)d_in[2];   // (3H,E)  fp32
    const float* bias = (const float*)d_in[3];   // (3H)    fp32
    float* out = (float*)d_out;                  // (B,H)   fp32

    cudaFuncSetAttribute(qrnn_gemm_kernel, cudaFuncAttributeMaxDynamicSharedMemorySize, SMEM_GEMM);
    cudaFuncSetAttribute(qrnn_scan_kernel, cudaFuncAttributeMaxDynamicSharedMemorySize, SMEM_SCAN);

    prep_all<<<(SENT_F4 + W_F4 + 255) / 256, 256>>>(sent, W);
    qrnn_gemm_kernel<<<dim3(H_DIM / HC, B_DIM), 128, SMEM_GEMM>>>(bias);
    qrnn_scan_kernel<<<dim3(H_DIM / HC, B_DIM), 128, SMEM_SCAN>>>(out);
}

// round 11
// speedup vs baseline: 1.2284x; 1.2284x over previous
#include <cuda_runtime.h>
#include <cuda_fp16.h>
#include <math.h>
#include <stdint.h>

// Problem dims
#define T_DIM 512
#define B_DIM 32
#define E_DIM 512
#define H_DIM 2048

// Tiling: CTA = 128 threads, 4 warps 1M x 4N, warp tile 64x24, CTA tile 64x96
#define HC  32          // h channels per CTA
#define NT  96          // GEMM N = 3*HC
#define MT  64          // t-chunk (GEMM M)
#define KC  64          // K elems per smem chunk (fp16 -> 128B rows)
#define NKC 8           // K chunks per t-chunk
#define NTC 8           // t-chunks
#define NCH (NTC * NKC) // 64 chunks

#define STR 26          // act row stride in halves (52B; 2-way worst-case conflicts)

// ---- smem layout (bytes) ----
#define SM_A    0                    // 2 x 8192   (A stages, fp16 SW128)
#define SM_B    16384                // 2 x 12288  (W stages, fp16 SW128, permuted cols)
#define SM_ACT  40960                // 4 warps x 64 x 26 x 2 = 13312
#define SM_BIAS 54272                // 96 floats = 384
#define SMEM_BYTES 54656             // x4 CTAs = 218624 <= 228KB

#define SWZ128(x) ((x) ^ (((x) >> 3) & 0x70))

// fp16 scratch (static device allocations — allowed)
__device__ __half g_sentH[B_DIM * T_DIM * E_DIM];   // (B,T,E) fp16
__device__ __half g_wH[3 * H_DIM * E_DIM];          // (3H,E)  fp16

// ---------------- helpers ----------------
__device__ __forceinline__ uint32_t smem_u32(const void* p) {
    uint32_t a;
    asm("{ .reg .u64 t; cvta.to.shared.u64 t, %1; cvt.u32.u64 %0, t; }" : "=r"(a) : "l"(p));
    return a;
}
__device__ __forceinline__ float tanh_hw(float x) {
    float y; asm("tanh.approx.f32 %0, %1;" : "=f"(y) : "f"(x)); return y;
}
__device__ __forceinline__ float sigmoid_hw(float x) {
    return fmaf(0.5f, tanh_hw(0.5f * x), 0.5f);
}
__device__ __forceinline__ void cp_async16(uint32_t dst, const void* src) {
    uint64_t g; asm("cvta.to.global.u64 %0, %1;" : "=l"(g) : "l"(src));
    asm volatile("cp.async.cg.shared.global [%0], [%1], 16;" :: "r"(dst), "l"(g) : "memory");
}
__device__ __forceinline__ void ldsm4(uint32_t* r, uint32_t addr) {
    asm volatile("ldmatrix.sync.aligned.m8n8.x4.shared.b16 {%0,%1,%2,%3}, [%4];"
                 : "=r"(r[0]), "=r"(r[1]), "=r"(r[2]), "=r"(r[3]) : "r"(addr));
}
__device__ __forceinline__ void ldsm2(uint32_t* r, uint32_t addr) {
    asm volatile("ldmatrix.sync.aligned.m8n8.x2.shared.b16 {%0,%1}, [%2];"
                 : "=r"(r[0]), "=r"(r[1]) : "r"(addr));
}
__device__ __forceinline__ void mma_f16(float* c, const uint32_t* a, const uint32_t* b) {
    asm volatile(
        "mma.sync.aligned.m16n8k16.row.col.f32.f16.f16.f32 "
        "{%0,%1,%2,%3}, {%4,%5,%6,%7}, {%8,%9}, {%0,%1,%2,%3};"
        : "+f"(c[0]), "+f"(c[1]), "+f"(c[2]), "+f"(c[3])
        : "r"(a[0]), "r"(a[1]), "r"(a[2]), "r"(a[3]), "r"(b[0]), "r"(b[1]));
}

// ---------- merged prepass: fp32 -> fp16; sent also transposed (T,B,E)->(B,T,E) ----------
#define SENT_F4 (T_DIM * B_DIM * E_DIM / 4)   // 2,097,152
#define W_F4    (3 * H_DIM * E_DIM / 4)       //   786,432
__global__ void __launch_bounds__(256) prep_all(const float* __restrict__ sent,
                                                const float* __restrict__ W) {
    int li = blockIdx.x * 256 + threadIdx.x;
    if (li < SENT_F4) {
        const float4 v = ((const float4*)sent)[li];
        int e4 = li & 127;
        int b  = (li >> 7) & 31;
        int t  = li >> 12;
        __half2* dst = (__half2*)(g_sentH + ((size_t)(b * T_DIM + t) * E_DIM + e4 * 4));
        dst[0] = __floats2half2_rn(v.x, v.y);
        dst[1] = __floats2half2_rn(v.z, v.w);
    } else if (li < SENT_F4 + W_F4) {
        int wi = li - SENT_F4;
        const float4 v = ((const float4*)W)[wi];
        __half2* dst = (__half2*)g_wH + (size_t)wi * 2;
        dst[0] = __floats2half2_rn(v.x, v.y);
        dst[1] = __floats2half2_rn(v.z, v.w);
    }
}

// -------- fused kernel: 128 thr, 4 warps 1M x 4N, warp tile 64x24, occ 4 --------
// W columns permuted per warp: staged row n -> warp w = n/24, r = n%24,
// grp = r/8 (z|f|o), c = r%8 -> physical W row grp*H + h0 + w*8 + c.
// Each warp owns channels [w*8, w*8+8) with z,f,o -> fully warp-local scan.
__global__ void __launch_bounds__(128, 4)
qrnn_f16_kernel(const float* __restrict__ bias, float* __restrict__ out)
{
    extern __shared__ char smem[];
    const uint32_t sb = smem_u32(smem);
    const int tid = threadIdx.x;
    const int bb  = blockIdx.y;
    const int h0  = blockIdx.x * HC;
    const int lane = tid & 31;
    const int wid  = tid >> 5;         // 0..3 (N quarter)
    const int g  = lane >> 2;
    const int tg = lane & 3;
    const int n_base = wid * 24;

    float*  sbias = (float*)(smem + SM_BIAS);       // local-col layout [w*24 + r]
    __half* actw  = (__half*)(smem + SM_ACT) + wid * (MT * STR);
    if (tid < 96) {
        int w = tid / 24, r = tid % 24;
        sbias[tid] = bias[(r >> 3) * H_DIM + h0 + w * 8 + (r & 7)];
    }

    const __half* Asrc = g_sentH + (size_t)bb * (T_DIM * E_DIM);

    // ldmatrix lane->address components
    const int am = lane >> 3;
    const int a_row_in = (am & 1) * 8 + (lane & 7);
    const int a_colb16 = (am >> 1) * 16;
    const int b_row_in = (am >> 1) * 8 + (lane & 7);
    const int b_colb16 = (am & 1) * 16;
    const int l16      = lane & 15;                 // x2 address lanes
    const int b2_row   = l16 & 7;
    const int b2_colb  = (l16 >> 3) * 16;

    auto stage = [&](int ch) {
        const int tc = ch >> 3, kc = ch & 7, buf = ch & 1;
        const __half* ab = Asrc + (size_t)(tc * MT) * E_DIM + kc * KC;
        const uint32_t aB = sb + SM_A + buf * 8192;
#pragma unroll
        for (int i = 0; i < 4; i++) {
            int l = i * 128 + tid;
            int row = l >> 3, c = l & 7;
            cp_async16(aB + (uint32_t)SWZ128(row * 128 + c * 16), ab + (size_t)row * E_DIM + c * 8);
        }
        const uint32_t bB = sb + SM_B + buf * 12288;
#pragma unroll
        for (int i = 0; i < 6; i++) {
            int l = i * 128 + tid;
            int n = l >> 3, c = l & 7;
            int w = n / 24, r = n % 24;
            int wrow = (r >> 3) * H_DIM + h0 + w * 8 + (r & 7);
            cp_async16(bB + (uint32_t)SWZ128(n * 128 + c * 16),
                       g_wH + (size_t)wrow * E_DIM + kc * KC + c * 8);
        }
        asm volatile("cp.async.commit_group;" ::: "memory");
    };

    // scan state: lane = (s = lane>>3 segment of 16 t, ch = lane&7 channel)
    const int s_id = lane >> 3;
    const int chn  = lane & 7;
    float c_carry = 0.0f;              // replicated across the 4 s-lanes per channel
    float m_state = -INFINITY;

    stage(0);

    for (int tc = 0; tc < NTC; tc++) {
        float acc[4][3][4];
#pragma unroll
        for (int mf = 0; mf < 4; mf++)
#pragma unroll
            for (int nf = 0; nf < 3; nf++)
#pragma unroll
                for (int q = 0; q < 4; q++) acc[mf][nf][q] = 0.0f;

        for (int kc = 0; kc < NKC; kc++) {
            const int ch  = tc * NKC + kc;
            const int buf = ch & 1;

            __syncthreads();   // alt buffer's MMA readers (chunk ch-1) done
            if (ch + 1 < NCH) {
                stage(ch + 1);
                asm volatile("cp.async.wait_group 1;" ::: "memory");
            } else {
                asm volatile("cp.async.wait_group 0;" ::: "memory");
            }
            __syncthreads();   // chunk ch fully staged

            const uint32_t aB = sb + SM_A + buf * 8192;
            const uint32_t bB = sb + SM_B + buf * 12288;
#pragma unroll
            for (int ks = 0; ks < 4; ks++) {     // 4 k16-steps over KC=64
                uint32_t a[4][4];
#pragma unroll
                for (int mf = 0; mf < 4; mf++)
                    ldsm4(a[mf], aB + (uint32_t)SWZ128((mf * 16 + a_row_in) * 128
                                                       + ks * 32 + a_colb16));
                uint32_t b[3][2];
                {
                    uint32_t r[4];
                    ldsm4(r, bB + (uint32_t)SWZ128((n_base + b_row_in) * 128
                                                   + ks * 32 + b_colb16));
                    b[0][0] = r[0]; b[0][1] = r[1];   // n 0-7  of warp
                    b[1][0] = r[2]; b[1][1] = r[3];   // n 8-15
                    uint32_t q[2];
                    ldsm2(q, bB + (uint32_t)SWZ128((n_base + 16 + b2_row) * 128
                                                   + ks * 32 + b2_colb));
                    b[2][0] = q[0]; b[2][1] = q[1];   // n 16-23
                }
#pragma unroll
                for (int mf = 0; mf < 4; mf++)
#pragma unroll
                    for (int nf = 0; nf < 3; nf++)
                        mma_f16(acc[mf][nf], a[mf], b[nf]);
            }
        }

        // ---- epilogue (warp-local): bias + activation -> actw[t][r], r = nf*8+col ----
#pragma unroll
        for (int mf = 0; mf < 4; mf++) {
            int r0 = mf * 16 + g;
#pragma unroll
            for (int nf = 0; nf < 3; nf++) {
                int jl = nf * 8 + tg * 2;
                float b0 = sbias[wid * 24 + jl];
                float b1 = sbias[wid * 24 + jl + 1];
#pragma unroll
                for (int rr = 0; rr < 2; rr++) {
                    int row  = r0 + rr * 8;
                    float v0 = acc[mf][nf][rr * 2 + 0] + b0;
                    float v1 = acc[mf][nf][rr * 2 + 1] + b1;
                    if (nf == 0) { v0 = tanh_hw(v0);    v1 = tanh_hw(v1); }
                    else         { v0 = sigmoid_hw(v0); v1 = sigmoid_hw(v1); }
                    *(__half2*)(actw + row * STR + jl) = __floats2half2_rn(v0, v1);
                }
            }
        }
        __syncwarp();

        // ---- warp-local segmented scan: s_id owns t [16*s_id, +16), chn = channel ----
        float A = 1.0f, B = 0.0f;
#pragma unroll
        for (int i = 0; i < 16; i++) {
            const __half* rp = actw + (s_id * 16 + i) * STR;
            float z = __half2float(rp[chn]);
            float f = __half2float(rp[8 + chn]);
            float a_ = 1.0f - f;
            A *= a_;
            B = fmaf(a_, B, f * z);
        }
        // inclusive compose-scan over segments (stride 8, 16 in lane space)
#pragma unroll
        for (int d = 8; d <= 16; d <<= 1) {
            float Au = __shfl_up_sync(0xffffffffu, A, d);
            float Bu = __shfl_up_sync(0xffffffffu, B, d);
            if (lane >= d) { B = fmaf(A, Bu, B); A *= Au; }
        }
        // entry state: exclusive prefix applied to carry
        float Ae = __shfl_up_sync(0xffffffffu, A, 8);
        float Be = __shfl_up_sync(0xffffffffu, B, 8);
        float c  = (s_id == 0) ? c_carry : fmaf(Ae, c_carry, Be);
        // pass 2: walk my 16 t's
#pragma unroll
        for (int i = 0; i < 16; i++) {
            const __half* rp = actw + (s_id * 16 + i) * STR;
            float z = __half2float(rp[chn]);
            float f = __half2float(rp[8 + chn]);
            float o = __half2float(rp[16 + chn]);
            c = fmaf(f, z - c, c);                 // c = f*z + (1-f)*c
            m_state = fmaxf(m_state, o * c);
        }
        // carry advance: full-chunk composition from segment-3 lane of this channel
        float At = __shfl_sync(0xffffffffu, A, 24 + chn);
        float Bt = __shfl_sync(0xffffffffu, B, 24 + chn);
        c_carry = fmaf(At, c_carry, Bt);
        // next t-chunk's k-loop barriers order act reads before overwrite
    }

    // combine max across the 4 segment-lanes of each channel; lanes 0-7 store
    m_state = fmaxf(m_state, __shfl_xor_sync(0xffffffffu, m_state, 8));
    m_state = fmaxf(m_state, __shfl_xor_sync(0xffffffffu, m_state, 16));
    if (lane < 8) out[bb * H_DIM + h0 + wid * 8 + chn] = m_state;
}

extern "C" void kernel_launch(void* const* d_in, const int* in_sizes, int n_in,
                              void* d_out, int out_size)
{
    (void)in_sizes; (void)n_in; (void)out_size;
    const float* sent = (const float*)d_in[0];   // (T,B,E) fp32
    const float* W    = (const float*)d_in[2];   // (3H,E)  fp32
    const float* bias = (const float*)d_in[3];   // (3H)    fp32
    float* out = (float*)d_out;                  // (B,H)   fp32

    cudaFuncSetAttribute(qrnn_f16_kernel, cudaFuncAttributeMaxDynamicSharedMemorySize, SMEM_BYTES);

    prep_all<<<(SENT_F4 + W_F4 + 255) / 256, 256>>>(sent, W);
    qrnn_f16_kernel<<<dim3(H_DIM / HC, B_DIM), 128, SMEM_BYTES>>>(bias, out);
}